// round 14
// baseline (speedup 1.0000x reference)
#include <cuda_runtime.h>

#define NBLK 444
#define D1_BLKS 496
#define BN_EPS 1e-3f

__device__ __align__(16) float g_buf1[16*128*128*8];   // conv1+pool out
__device__ __align__(16) float g_buf2[16*64*64*16];    // conv2+pool out
__device__ __align__(16) float g_xintp[16*32*32*32];   // conv3+pool out, padded: slot 1+c
__device__ __align__(16) float g_f1p[D1_BLKS*16*64];   // dense1 partials
__device__ __align__(16) float g_theta[16*8];          // theta padded to 8/b
__device__ unsigned g_ctr[8];                          // monotonic barrier counters

// ---- f32x2 helpers ----
#define FFMA2(d,a,b,c) asm("fma.rn.f32x2 %0,%1,%2,%3;" : "=l"(d) : "l"(a), "l"(b), "l"(c))
#define PK2(d,lo,hi)   asm("mov.b64 %0,{%1,%2};" : "=l"(d) : "r"(__float_as_uint(lo)), "r"(__float_as_uint(hi)))
#define UNPK2(lo,hi,v) do { unsigned _l,_h; asm("mov.b64 {%0,%1},%2;" : "=r"(_l), "=r"(_h) : "l"(v)); lo=__uint_as_float(_l); hi=__uint_as_float(_h); } while(0)

// Monotonic grid barrier: replay-safe (no reset), acquire/release via threadfence.
__device__ __forceinline__ void gridbar(int i){
    __syncthreads();
    if (threadIdx.x == 0){
        __threadfence();
        unsigned a = atomicAdd(&g_ctr[i], 1u) + 1u;
        unsigned target = ((a + NBLK - 1u) / NBLK) * NBLK;
        while (*((volatile unsigned*)&g_ctr[i]) < target) __nanosleep(64);
        __threadfence();
    }
    __syncthreads();
}

union __align__(16) SmemU {
    struct { float sp[34*36]; float sk[72]; float sb[8]; } c1;
    struct { float sp[8][10*36]; float sw[1152]; float sb[16]; } c2;
    struct { float sp[16][10*20]; float sw[9*16*32]; float sb[32]; } c3;
    struct { float fsm[64*16]; float wsm[64*64]; } d1;
    struct { float red[4][64]; float h1[64]; float h2[96]; } dr;
};

__global__ void __launch_bounds__(256,4) fused_k(
    const float* __restrict__ x,
    const float* __restrict__ c1k, const float* __restrict__ c1b,
    const float* __restrict__ c2k, const float* __restrict__ c2b,
    const float* __restrict__ c3k, const float* __restrict__ c3b,
    const float* __restrict__ bng, const float* __restrict__ bnb,
    const float* __restrict__ bnm, const float* __restrict__ bnv,
    const float* __restrict__ d1k, const float* __restrict__ d1b,
    const float* __restrict__ d2k, const float* __restrict__ d2b,
    const float* __restrict__ d3k, const float* __restrict__ d3b,
    float* __restrict__ out)
{
    __shared__ SmemU S;
    int tid = threadIdx.x;

    // ================= stage 1: conv1 (1->8) + relu + maxpool =================
    for (int t = blockIdx.x; t < 1024; t += NBLK){
        int bx = t & 7, by = (t>>3)&7, b = t>>6;
        int px0 = bx*16, py0 = by*16;
        int iy0 = py0*2-1, ix0 = px0*2-1;
        for (int idx = tid; idx < 34*34; idx += 256) {
            int yy = idx/34, xx = idx-yy*34;
            int gy = iy0+yy, gx = ix0+xx;
            float v = 0.f;
            if ((unsigned)gy < 256u && (unsigned)gx < 256u) v = x[(b*256+gy)*256+gx];
            S.c1.sp[yy*36+xx] = v;
        }
        if (tid < 72) S.c1.sk[tid] = c1k[tid];
        if (tid < 8)  S.c1.sb[tid] = c1b[tid];
        __syncthreads();
        int tx = tid & 15, ty = tid >> 4;
        float p[4][4];
        #pragma unroll
        for (int r=0;r<4;r++)
          #pragma unroll
          for (int c=0;c<4;c++)
            p[r][c] = S.c1.sp[(ty*2+r)*36 + tx*2+c];
        float o[8];
        #pragma unroll
        for (int co=0;co<8;co++){
            float w[9];
            #pragma unroll
            for (int q=0;q<9;q++) w[q]=S.c1.sk[q*8+co];
            float s00=0.f,s01=0.f,s10=0.f,s11=0.f;
            #pragma unroll
            for (int r=0;r<3;r++)
              #pragma unroll
              for (int c=0;c<3;c++){
                float wv = w[r*3+c];
                s00 += p[r][c]*wv;
                s01 += p[r][c+1]*wv;
                s10 += p[r+1][c]*wv;
                s11 += p[r+1][c+1]*wv;
              }
            float m = fmaxf(fmaxf(s00,s01),fmaxf(s10,s11)) + S.c1.sb[co];
            o[co] = fmaxf(m, 0.f);
        }
        int py = py0+ty, px = px0+tx;
        float4* outp = (float4*)&g_buf1[((b*128+py)*128+px)*8];
        outp[0] = make_float4(o[0],o[1],o[2],o[3]);
        outp[1] = make_float4(o[4],o[5],o[6],o[7]);
        __syncthreads();
    }
    gridbar(0);

    // ================= stage 2: conv2 (8->16) + relu + maxpool =================
    for (int t = blockIdx.x; t < 1024; t += NBLK){
        int bx = t & 3, by = (t>>2)&15, b = t>>6;
        int px0 = bx*16, py0 = by*4;
        int iy0 = py0*2-1, ix0 = px0*2-1;
        for (int idx=tid; idx<10*34*2; idx+=256){
            int q = idx & 1; int pix = idx >> 1;
            int yy = pix/34, xx = pix - yy*34;
            int gy = iy0+yy, gx = ix0+xx;
            float4 v = make_float4(0.f,0.f,0.f,0.f);
            if ((unsigned)gy<128u && (unsigned)gx<128u)
                v = *(const float4*)&g_buf1[((b*128+gy)*128+gx)*8 + q*4];
            int off = yy*36+xx;
            S.c2.sp[q*4+0][off]=v.x; S.c2.sp[q*4+1][off]=v.y;
            S.c2.sp[q*4+2][off]=v.z; S.c2.sp[q*4+3][off]=v.w;
        }
        for (int idx=tid; idx<1152; idx+=256) S.c2.sw[idx]=c2k[idx];
        if (tid<16) S.c2.sb[tid]=c2b[tid];
        __syncthreads();
        int g = tid>>6; int pid = tid & 63;
        int tx = pid & 15, ty = pid >> 4;
        int cobase = g*4;
        unsigned long long acc2[4][2];
        #pragma unroll
        for (int p_=0;p_<4;p_++){ acc2[p_][0]=0ull; acc2[p_][1]=0ull; }
        #pragma unroll 1
        for (int ci=0;ci<8;ci++){
            const float* pl = &S.c2.sp[ci][(ty*2)*36 + tx*2];
            float W[4][4];
            float2* Wp = (float2*)W;
            #pragma unroll
            for (int r=0;r<4;r++){
                Wp[r*2]   = *(const float2*)&pl[r*36];
                Wp[r*2+1] = *(const float2*)&pl[r*36+2];
            }
            #pragma unroll
            for (int q=0;q<9;q++){
                int dy=q/3, dx=q-3*dy;
                ulonglong2 w2 = *(const ulonglong2*)&S.c2.sw[(q*8+ci)*16 + cobase];
                unsigned long long p00,p01,p10,p11;
                PK2(p00,W[dy][dx],  W[dy][dx]);
                PK2(p01,W[dy][dx+1],W[dy][dx+1]);
                PK2(p10,W[dy+1][dx],  W[dy+1][dx]);
                PK2(p11,W[dy+1][dx+1],W[dy+1][dx+1]);
                FFMA2(acc2[0][0],p00,w2.x,acc2[0][0]); FFMA2(acc2[0][1],p00,w2.y,acc2[0][1]);
                FFMA2(acc2[1][0],p01,w2.x,acc2[1][0]); FFMA2(acc2[1][1],p01,w2.y,acc2[1][1]);
                FFMA2(acc2[2][0],p10,w2.x,acc2[2][0]); FFMA2(acc2[2][1],p10,w2.y,acc2[2][1]);
                FFMA2(acc2[3][0],p11,w2.x,acc2[3][0]); FFMA2(acc2[3][1],p11,w2.y,acc2[3][1]);
            }
        }
        int py=py0+ty, px=px0+tx;
        float4 o;
        {
            float a0,a1,b0,b1,c0,c1,d0,d1;
            UNPK2(a0,a1,acc2[0][0]); UNPK2(b0,b1,acc2[1][0]);
            UNPK2(c0,c1,acc2[2][0]); UNPK2(d0,d1,acc2[3][0]);
            o.x = fmaxf(fmaxf(fmaxf(a0,b0),fmaxf(c0,d0))+S.c2.sb[cobase+0],0.f);
            o.y = fmaxf(fmaxf(fmaxf(a1,b1),fmaxf(c1,d1))+S.c2.sb[cobase+1],0.f);
        }
        {
            float a0,a1,b0,b1,c0,c1,d0,d1;
            UNPK2(a0,a1,acc2[0][1]); UNPK2(b0,b1,acc2[1][1]);
            UNPK2(c0,c1,acc2[2][1]); UNPK2(d0,d1,acc2[3][1]);
            o.z = fmaxf(fmaxf(fmaxf(a0,b0),fmaxf(c0,d0))+S.c2.sb[cobase+2],0.f);
            o.w = fmaxf(fmaxf(fmaxf(a1,b1),fmaxf(c1,d1))+S.c2.sb[cobase+3],0.f);
        }
        *(float4*)&g_buf2[((b*64+py)*64+px)*16 + cobase] = o;
        __syncthreads();
    }
    gridbar(1);

    // ================= stage 3: conv3 (16->31) + relu + maxpool =================
    for (int t = blockIdx.x; t < 512; t += NBLK){
        int bx = t & 3, by = (t>>2)&7, b = t>>5;
        int px0 = bx*8, py0 = by*4;
        int iy0 = py0*2-1, ix0 = px0*2-1;
        for (int idx=tid; idx<10*18*4; idx+=256){
            int q = idx & 3; int pix = idx >> 2;
            int yy=pix/18, xx=pix-yy*18;
            int gy=iy0+yy, gx=ix0+xx;
            float4 v=make_float4(0.f,0.f,0.f,0.f);
            if ((unsigned)gy<64u && (unsigned)gx<64u)
                v = *(const float4*)&g_buf2[((b*64+gy)*64+gx)*16 + q*4];
            int off=yy*20+xx;
            S.c3.sp[q*4+0][off]=v.x; S.c3.sp[q*4+1][off]=v.y;
            S.c3.sp[q*4+2][off]=v.z; S.c3.sp[q*4+3][off]=v.w;
        }
        for (int idx=tid; idx<9*16*32; idx+=256){
            int co = idx & 31; int tc = idx >> 5;
            S.c3.sw[idx] = (co<31) ? c3k[tc*31+co] : 0.f;
        }
        if (tid<32) S.c3.sb[tid] = (tid<31)? c3b[tid] : 0.f;
        __syncthreads();
        int g = tid>>5; int pid = tid&31; int tx=pid&7, ty=pid>>3;
        int cobase = g*4;
        unsigned long long acc2[4][2];
        #pragma unroll
        for (int p_=0;p_<4;p_++){ acc2[p_][0]=0ull; acc2[p_][1]=0ull; }
        #pragma unroll 1
        for (int ci=0;ci<16;ci++){
            const float* pl = &S.c3.sp[ci][(ty*2)*20 + tx*2];
            float W[4][4];
            float2* Wp = (float2*)W;
            #pragma unroll
            for (int r=0;r<4;r++){
                Wp[r*2]   = *(const float2*)&pl[r*20];
                Wp[r*2+1] = *(const float2*)&pl[r*20+2];
            }
            #pragma unroll
            for (int q=0;q<9;q++){
                int dy=q/3, dx=q-3*dy;
                ulonglong2 w2 = *(const ulonglong2*)&S.c3.sw[(q*16+ci)*32+cobase];
                unsigned long long p00,p01,p10,p11;
                PK2(p00,W[dy][dx],  W[dy][dx]);
                PK2(p01,W[dy][dx+1],W[dy][dx+1]);
                PK2(p10,W[dy+1][dx],  W[dy+1][dx]);
                PK2(p11,W[dy+1][dx+1],W[dy+1][dx+1]);
                FFMA2(acc2[0][0],p00,w2.x,acc2[0][0]); FFMA2(acc2[0][1],p00,w2.y,acc2[0][1]);
                FFMA2(acc2[1][0],p01,w2.x,acc2[1][0]); FFMA2(acc2[1][1],p01,w2.y,acc2[1][1]);
                FFMA2(acc2[2][0],p10,w2.x,acc2[2][0]); FFMA2(acc2[2][1],p10,w2.y,acc2[2][1]);
                FFMA2(acc2[3][0],p11,w2.x,acc2[3][0]); FFMA2(acc2[3][1],p11,w2.y,acc2[3][1]);
            }
        }
        int py=py0+ty, px=px0+tx;
        float* outp = &g_xintp[((b*32+py)*32+px)*32];
        #pragma unroll
        for (int kk=0;kk<2;kk++){
            float a0,a1,b0,b1,c0,c1,d0,d1;
            UNPK2(a0,a1,acc2[0][kk]); UNPK2(b0,b1,acc2[1][kk]);
            UNPK2(c0,c1,acc2[2][kk]); UNPK2(d0,d1,acc2[3][kk]);
            int co0 = cobase+kk*2, co1 = cobase+kk*2+1;
            float m0 = fmaxf(fmaxf(a0,b0),fmaxf(c0,d0))+S.c3.sb[co0];
            float m1 = fmaxf(fmaxf(a1,b1),fmaxf(c1,d1))+S.c3.sb[co1];
            if (co0<31) outp[1+co0] = fmaxf(m0,0.f);
            if (co1<31) outp[1+co1] = fmaxf(m1,0.f);
        }
        __syncthreads();
    }
    gridbar(2);

    // ================= stage 4: dense1 (BN + GEMM split-K) =================
    for (int t = blockIdx.x; t < D1_BLKS; t += NBLK){
        int i0 = t*64;
        {
            const float4* wsrc = (const float4*)&d1k[i0*64];
            float4* wdst = (float4*)S.d1.wsm;
            #pragma unroll
            for (int r=0;r<4;r++)
                wdst[tid + r*256] = wsrc[tid + r*256];
        }
        #pragma unroll
        for (int r=0;r<4;r++){
            int idx = tid + r*256;
            int il = idx>>4; int bb = idx & 15;
            int i = i0+il;
            int cell = i/31; int c = i - cell*31;
            float xv = g_xintp[bb*32768 + cell*32 + 1 + c];
            S.d1.fsm[il*16+bb] = (xv - bnm[i]) * rsqrtf(bnv[i]+BN_EPS) * bng[i] + bnb[i];
        }
        __syncthreads();
        int j = tid & 63, bg = tid>>6;
        float a0=0.f,a1=0.f,a2=0.f,a3=0.f;
        #pragma unroll 8
        for (int il=0; il<64; il++){
            float w = S.d1.wsm[il*64 + j];
            float4 f = *(const float4*)&S.d1.fsm[il*16 + bg*4];
            a0 += f.x*w; a1 += f.y*w; a2 += f.z*w; a3 += f.w*w;
        }
        float* o = &g_f1p[t*1024];
        o[(bg*4+0)*64+j] = a0;
        o[(bg*4+1)*64+j] = a1;
        o[(bg*4+2)*64+j] = a2;
        o[(bg*4+3)*64+j] = a3;
        __syncthreads();
    }
    gridbar(3);

    // ================= stage 5: reduce + dense2 + dense3 -> theta =================
    for (int t = blockIdx.x; t < 16; t += NBLK){
        int b = t;
        int j = tid & 63, g = tid>>6;
        float s = 0.f;
        #pragma unroll 4
        for (int p=g; p<D1_BLKS; p+=4) s += g_f1p[p*1024 + b*64 + j];
        S.dr.red[g][j] = s;
        __syncthreads();
        if (tid<64)
            S.dr.h1[tid] = fmaxf(S.dr.red[0][tid]+S.dr.red[1][tid]+S.dr.red[2][tid]+S.dr.red[3][tid] + d1b[tid], 0.f);
        __syncthreads();
        if (tid<96){
            float s2 = d2b[tid];
            for (int i=0;i<64;i++) s2 += S.dr.h1[i]*d2k[i*96+tid];
            S.dr.h2[tid] = fmaxf(s2,0.f);
        }
        __syncthreads();
        if (tid<6){
            float s3 = d3b[tid];
            for (int i=0;i<96;i++) s3 += S.dr.h2[i]*d3k[i*6+tid];
            g_theta[b*8+tid] = s3;
        }
        __syncthreads();
    }
    gridbar(4);

    // ================= stage 6: sampler (grid+resize+concat+bilinear+leaky) =====
    for (int t = blockIdx.x; t < 32768; t += NBLK){
        int pix = t*32 + (tid>>3);
        int q = tid & 7;
        int b = pix >> 16;
        int h = (pix >> 8) & 255;
        int w = pix & 255;
        float4 t03 = *(const float4*)&g_theta[b*8];
        float2 t45 = *(const float2*)&g_theta[b*8+4];
        float gx = (float)w*(2.f/255.f) - 1.f;
        float gy = (float)h*(2.f/255.f) - 1.f;
        float tx = gx*t03.x + gy*t03.w + t03.z;
        float ty = gx*t03.y + gy*t45.x + t45.y;
        float xf = 0.5f*((tx+1.f)*255.f);
        float yf = 0.5f*((ty+1.f)*255.f);
        float x0f = floorf(xf), y0f = floorf(yf);
        float x0c = fminf(fmaxf(x0f,0.f),255.f);
        float x1c = fminf(fmaxf(x0f+1.f,0.f),255.f);
        float y0c = fminf(fmaxf(y0f,0.f),255.f);
        float y1c = fminf(fmaxf(y0f+1.f,0.f),255.f);
        float wa=(x1c-xf)*(y1c-yf), wb=(x1c-xf)*(yf-y0c);
        float wc=(xf-x0c)*(y1c-yf), wd=(xf-x0c)*(yf-y0c);
        int xi0=(int)x0c, xi1=(int)x1c, yi0=(int)y0c, yi1=(int)y1c;

        const float* xb = &g_xintp[b*32768];
        int ca = ((yi0>>3)*32 + (xi0>>3))*32;
        int cb = ((yi1>>3)*32 + (xi0>>3))*32;
        int cc = ((yi0>>3)*32 + (xi1>>3))*32;
        int cd = ((yi1>>3)*32 + (xi1>>3))*32;
        float4 Ia = *(const float4*)&xb[ca + q*4];
        float4 Ib = (cb==ca) ? Ia : *(const float4*)&xb[cb + q*4];
        float4 Ic = (cc==ca) ? Ia : *(const float4*)&xb[cc + q*4];
        float4 Id;
        if (cd==cb)      Id = Ib;
        else if (cd==cc) Id = Ic;
        else             Id = *(const float4*)&xb[cd + q*4];

        float4 val;
        val.x = wa*Ia.x + wb*Ib.x + wc*Ic.x + wd*Id.x;
        val.y = wa*Ia.y + wb*Ib.y + wc*Ic.y + wd*Id.y;
        val.z = wa*Ia.z + wb*Ib.z + wc*Ic.z + wd*Id.z;
        val.w = wa*Ia.w + wb*Ib.w + wc*Ic.w + wd*Id.w;

        if (q==0){
            const float* xb0 = x + b*65536;
            val.x = wa*xb0[yi0*256+xi0] + wb*xb0[yi1*256+xi0]
                  + wc*xb0[yi0*256+xi1] + wd*xb0[yi1*256+xi1];
        }
        val.x = (val.x>=0.f)? val.x : 0.1f*val.x;
        val.y = (val.y>=0.f)? val.y : 0.1f*val.y;
        val.z = (val.z>=0.f)? val.z : 0.1f*val.z;
        val.w = (val.w>=0.f)? val.w : 0.1f*val.w;
        *(float4*)&out[pix*32 + q*4] = val;
    }
}

extern "C" void kernel_launch(void* const* d_in, const int* in_sizes, int n_in,
                              void* d_out, int out_size)
{
    const float* x   = (const float*)d_in[0];
    const float* c1k = (const float*)d_in[1];
    const float* c1b = (const float*)d_in[2];
    const float* c2k = (const float*)d_in[3];
    const float* c2b = (const float*)d_in[4];
    const float* c3k = (const float*)d_in[5];
    const float* c3b = (const float*)d_in[6];
    const float* bng = (const float*)d_in[7];
    const float* bnb = (const float*)d_in[8];
    const float* bnm = (const float*)d_in[9];
    const float* bnv = (const float*)d_in[10];
    const float* d1k = (const float*)d_in[11];
    const float* d1b = (const float*)d_in[12];
    const float* d2k = (const float*)d_in[13];
    const float* d2b = (const float*)d_in[14];
    const float* d3k = (const float*)d_in[15];
    const float* d3b = (const float*)d_in[16];
    float* out = (float*)d_out;

    fused_k<<<NBLK, 256>>>(x, c1k, c1b, c2k, c2b, c3k, c3b,
                           bng, bnb, bnm, bnv,
                           d1k, d1b, d2k, d2b, d3k, d3b, out);
}

// round 15
// speedup vs baseline: 1.1444x; 1.1444x over previous
#include <cuda_runtime.h>

#define FEAT (32*32*31)   // 31744
#define BN_EPS 1e-3f
#define D1_BLKS 496        // 31744 / 64

__device__ __align__(16) float g_buf1[16*128*128*8];   // conv1+pool out
__device__ __align__(16) float g_buf2[16*64*64*16];    // conv2+pool out
__device__ __align__(16) float g_xintp[16*32*32*32];   // conv3+pool out, padded: slot 1+c
__device__ __align__(16) float g_f1p[D1_BLKS*16*64];   // dense1 partials
__device__ __align__(16) float g_theta[16*8];          // theta padded to 8/b

// ---- f32x2 helpers ----
#define FFMA2(d,a,b,c) asm("fma.rn.f32x2 %0,%1,%2,%3;" : "=l"(d) : "l"(a), "l"(b), "l"(c))
#define PK2(d,lo,hi)   asm("mov.b64 %0,{%1,%2};" : "=l"(d) : "r"(__float_as_uint(lo)), "r"(__float_as_uint(hi)))
#define UNPK2(lo,hi,v) do { unsigned _l,_h; asm("mov.b64 {%0,%1},%2;" : "=r"(_l), "=r"(_h) : "l"(v)); lo=__uint_as_float(_l); hi=__uint_as_float(_h); } while(0)

// ---------------- conv1 (1->8) + relu + maxpool2 (single launch) ----------------
__global__ void conv1pool_k(const float* __restrict__ x,
                            const float* __restrict__ k,
                            const float* __restrict__ bias)
{
    __shared__ float sp[34*36];
    __shared__ float sk[72];
    __shared__ float sb[8];
    int b = blockIdx.z;
    int px0 = blockIdx.x*16, py0 = blockIdx.y*16;
    int tid = threadIdx.y*16+threadIdx.x;
    int iy0 = py0*2-1, ix0 = px0*2-1;
    for (int idx = tid; idx < 34*34; idx += 256) {
        int yy = idx/34, xx = idx-yy*34;
        int gy = iy0+yy, gx = ix0+xx;
        float v = 0.f;
        if ((unsigned)gy < 256u && (unsigned)gx < 256u) v = x[(b*256+gy)*256+gx];
        sp[yy*36+xx] = v;
    }
    if (tid < 72) sk[tid] = k[tid];
    if (tid < 8)  sb[tid] = bias[tid];
    __syncthreads();
    int tx = threadIdx.x, ty = threadIdx.y;
    float p[4][4];
    #pragma unroll
    for (int r=0;r<4;r++)
      #pragma unroll
      for (int c=0;c<4;c++)
        p[r][c] = sp[(ty*2+r)*36 + tx*2+c];
    float o[8];
    #pragma unroll
    for (int co=0;co<8;co++){
        float w[9];
        #pragma unroll
        for (int t=0;t<9;t++) w[t]=sk[t*8+co];
        float s00=0.f,s01=0.f,s10=0.f,s11=0.f;
        #pragma unroll
        for (int r=0;r<3;r++)
          #pragma unroll
          for (int c=0;c<3;c++){
            float wv = w[r*3+c];
            s00 += p[r][c]*wv;
            s01 += p[r][c+1]*wv;
            s10 += p[r+1][c]*wv;
            s11 += p[r+1][c+1]*wv;
          }
        float m = fmaxf(fmaxf(s00,s01),fmaxf(s10,s11)) + sb[co];
        o[co] = fmaxf(m, 0.f);
    }
    int py = py0+ty, px = px0+tx;
    float4* outp = (float4*)&g_buf1[((b*128+py)*128+px)*8];
    outp[0] = make_float4(o[0],o[1],o[2],o[3]);
    outp[1] = make_float4(o[4],o[5],o[6],o[7]);
}

// ---------------- conv2 (8->16) + relu + maxpool2 ----------------
// 512 thr = 128 pooled px (8 rows x 16 cols) x 4 co-groups (4 co each).
// Register-blocked 4x4 window per ci: 8x LDS.64, taps run from registers.
__global__ void __launch_bounds__(512) conv2pool_k(const float* __restrict__ k,
                                                   const float* __restrict__ bias)
{
    __shared__ __align__(16) float sp[8][18*36];
    __shared__ __align__(16) float sw[1152];
    __shared__ float sb[16];
    int b = blockIdx.z;
    int px0 = blockIdx.x*16, py0 = blockIdx.y*8;
    int tid = threadIdx.x;
    int iy0 = py0*2-1, ix0 = px0*2-1;
    for (int idx=tid; idx<18*34*2; idx+=512){
        int q = idx & 1; int pix = idx >> 1;
        int yy = pix/34, xx = pix - yy*34;
        int gy = iy0+yy, gx = ix0+xx;
        float4 v = make_float4(0.f,0.f,0.f,0.f);
        if ((unsigned)gy<128u && (unsigned)gx<128u)
            v = *(const float4*)&g_buf1[((b*128+gy)*128+gx)*8 + q*4];
        int off = yy*36+xx;
        sp[q*4+0][off]=v.x; sp[q*4+1][off]=v.y; sp[q*4+2][off]=v.z; sp[q*4+3][off]=v.w;
    }
    for (int idx=tid; idx<1152; idx+=512) sw[idx]=k[idx];
    if (tid<16) sb[tid]=bias[tid];
    __syncthreads();
    int g = tid>>7; int pid = tid & 127;
    int tx = pid & 15, ty = pid >> 4;
    int cobase = g*4;
    unsigned long long acc2[4][2];
    #pragma unroll
    for (int p_=0;p_<4;p_++){ acc2[p_][0]=0ull; acc2[p_][1]=0ull; }

    #pragma unroll 1
    for (int ci=0;ci<8;ci++){
        const float* pl = &sp[ci][(ty*2)*36 + tx*2];
        float W[4][4];
        float2* Wp = (float2*)W;
        #pragma unroll
        for (int r=0;r<4;r++){
            Wp[r*2]   = *(const float2*)&pl[r*36];
            Wp[r*2+1] = *(const float2*)&pl[r*36+2];
        }
        #pragma unroll
        for (int t=0;t<9;t++){
            int dy=t/3, dx=t-3*dy;
            const unsigned long long* wp = (const unsigned long long*)&sw[(t*8+ci)*16 + cobase];
            unsigned long long w20=wp[0], w21=wp[1];
            unsigned long long p00,p01,p10,p11;
            PK2(p00,W[dy][dx],  W[dy][dx]);
            PK2(p01,W[dy][dx+1],W[dy][dx+1]);
            PK2(p10,W[dy+1][dx],  W[dy+1][dx]);
            PK2(p11,W[dy+1][dx+1],W[dy+1][dx+1]);
            FFMA2(acc2[0][0],p00,w20,acc2[0][0]); FFMA2(acc2[0][1],p00,w21,acc2[0][1]);
            FFMA2(acc2[1][0],p01,w20,acc2[1][0]); FFMA2(acc2[1][1],p01,w21,acc2[1][1]);
            FFMA2(acc2[2][0],p10,w20,acc2[2][0]); FFMA2(acc2[2][1],p10,w21,acc2[2][1]);
            FFMA2(acc2[3][0],p11,w20,acc2[3][0]); FFMA2(acc2[3][1],p11,w21,acc2[3][1]);
        }
    }
    int py=py0+ty, px=px0+tx;
    float4 o;
    {
        float a0,a1,b0,b1,c0,c1,d0,d1;
        UNPK2(a0,a1,acc2[0][0]); UNPK2(b0,b1,acc2[1][0]);
        UNPK2(c0,c1,acc2[2][0]); UNPK2(d0,d1,acc2[3][0]);
        o.x = fmaxf(fmaxf(fmaxf(a0,b0),fmaxf(c0,d0))+sb[cobase+0],0.f);
        o.y = fmaxf(fmaxf(fmaxf(a1,b1),fmaxf(c1,d1))+sb[cobase+1],0.f);
    }
    {
        float a0,a1,b0,b1,c0,c1,d0,d1;
        UNPK2(a0,a1,acc2[0][1]); UNPK2(b0,b1,acc2[1][1]);
        UNPK2(c0,c1,acc2[2][1]); UNPK2(d0,d1,acc2[3][1]);
        o.z = fmaxf(fmaxf(fmaxf(a0,b0),fmaxf(c0,d0))+sb[cobase+2],0.f);
        o.w = fmaxf(fmaxf(fmaxf(a1,b1),fmaxf(c1,d1))+sb[cobase+3],0.f);
    }
    *(float4*)&g_buf2[((b*64+py)*64+px)*16 + cobase] = o;
}

// ---------------- conv3 (16->31) + relu + maxpool2 ----------------
// 512 thr = 64 pooled px (8x8) x 8 co-groups (4 co each), register-blocked window.
__global__ void __launch_bounds__(512) conv3pool_k(const float* __restrict__ k,
                                                   const float* __restrict__ bias)
{
    __shared__ __align__(16) float sp[16][18*20];
    __shared__ __align__(16) float sw[9*16*32];   // co padded to 32
    __shared__ float sb[32];
    int b = blockIdx.z;
    int px0 = blockIdx.x*8, py0 = blockIdx.y*8;
    int tid = threadIdx.x;
    int iy0 = py0*2-1, ix0 = px0*2-1;
    for (int idx=tid; idx<18*18*4; idx+=512){
        int q = idx & 3; int pix = idx >> 2;
        int yy=pix/18, xx=pix-yy*18;
        int gy=iy0+yy, gx=ix0+xx;
        float4 v=make_float4(0.f,0.f,0.f,0.f);
        if ((unsigned)gy<64u && (unsigned)gx<64u)
            v = *(const float4*)&g_buf2[((b*64+gy)*64+gx)*16 + q*4];
        int off=yy*20+xx;
        sp[q*4+0][off]=v.x; sp[q*4+1][off]=v.y; sp[q*4+2][off]=v.z; sp[q*4+3][off]=v.w;
    }
    for (int idx=tid; idx<9*16*32; idx+=512){
        int co = idx & 31; int tc = idx >> 5;
        sw[idx] = (co<31) ? k[tc*31+co] : 0.f;
    }
    if (tid<32) sb[tid] = (tid<31)? bias[tid] : 0.f;
    __syncthreads();
    int g = tid>>6; int pid = tid&63; int tx=pid&7, ty=pid>>3;
    int cobase = g*4;
    unsigned long long acc2[4][2];
    #pragma unroll
    for (int p_=0;p_<4;p_++){ acc2[p_][0]=0ull; acc2[p_][1]=0ull; }

    #pragma unroll 1
    for (int ci=0;ci<16;ci++){
        const float* pl = &sp[ci][(ty*2)*20 + tx*2];
        float W[4][4];
        float2* Wp = (float2*)W;
        #pragma unroll
        for (int r=0;r<4;r++){
            Wp[r*2]   = *(const float2*)&pl[r*20];
            Wp[r*2+1] = *(const float2*)&pl[r*20+2];
        }
        #pragma unroll
        for (int t=0;t<9;t++){
            int dy=t/3, dx=t-3*dy;
            const unsigned long long* wp = (const unsigned long long*)&sw[(t*16+ci)*32+cobase];
            unsigned long long w20=wp[0], w21=wp[1];
            unsigned long long p00,p01,p10,p11;
            PK2(p00,W[dy][dx],  W[dy][dx]);
            PK2(p01,W[dy][dx+1],W[dy][dx+1]);
            PK2(p10,W[dy+1][dx],  W[dy+1][dx]);
            PK2(p11,W[dy+1][dx+1],W[dy+1][dx+1]);
            FFMA2(acc2[0][0],p00,w20,acc2[0][0]); FFMA2(acc2[0][1],p00,w21,acc2[0][1]);
            FFMA2(acc2[1][0],p01,w20,acc2[1][0]); FFMA2(acc2[1][1],p01,w21,acc2[1][1]);
            FFMA2(acc2[2][0],p10,w20,acc2[2][0]); FFMA2(acc2[2][1],p10,w21,acc2[2][1]);
            FFMA2(acc2[3][0],p11,w20,acc2[3][0]); FFMA2(acc2[3][1],p11,w21,acc2[3][1]);
        }
    }
    int py=py0+ty, px=px0+tx;
    float* outp = &g_xintp[((b*32+py)*32+px)*32];   // padded: slot 1+co
    #pragma unroll
    for (int kk=0;kk<2;kk++){
        float a0,a1,b0,b1,c0,c1,d0,d1;
        UNPK2(a0,a1,acc2[0][kk]); UNPK2(b0,b1,acc2[1][kk]);
        UNPK2(c0,c1,acc2[2][kk]); UNPK2(d0,d1,acc2[3][kk]);
        int co0 = cobase+kk*2, co1 = cobase+kk*2+1;
        float m0 = fmaxf(fmaxf(a0,b0),fmaxf(c0,d0))+sb[co0];
        float m1 = fmaxf(fmaxf(a1,b1),fmaxf(c1,d1))+sb[co1];
        if (co0<31) outp[1+co0] = fmaxf(m0,0.f);
        if (co1<31) outp[1+co1] = fmaxf(m1,0.f);
    }
}

// ---------------- dense1: BN + (16x31744)@(31744x64), staged split-K ----------------
__global__ void __launch_bounds__(256) dense1_k(const float* __restrict__ gamma,
                                                const float* __restrict__ beta,
                                                const float* __restrict__ mean,
                                                const float* __restrict__ var,
                                                const float* __restrict__ Wd)
{
    __shared__ __align__(16) float fsm[64*16];
    __shared__ __align__(16) float wsm[64*64];
    int i0 = blockIdx.x*64;
    int tid = threadIdx.x;
    {
        const float4* wsrc = (const float4*)&Wd[i0*64];
        float4* wdst = (float4*)wsm;
        #pragma unroll
        for (int r=0;r<4;r++)
            wdst[tid + r*256] = wsrc[tid + r*256];
    }
    #pragma unroll
    for (int r=0;r<4;r++){
        int idx = tid + r*256;
        int il = idx>>4; int bb = idx & 15;
        int i = i0+il;
        int cell = i/31; int c = i - cell*31;
        float xv = g_xintp[bb*32768 + cell*32 + 1 + c];
        fsm[il*16+bb] = (xv - mean[i]) * rsqrtf(var[i]+BN_EPS) * gamma[i] + beta[i];
    }
    __syncthreads();
    int j = tid & 63, bg = tid>>6;
    float a0=0.f,a1=0.f,a2=0.f,a3=0.f;
    #pragma unroll 8
    for (int il=0; il<64; il++){
        float w = wsm[il*64 + j];
        float4 f = *(const float4*)&fsm[il*16 + bg*4];
        a0 += f.x*w; a1 += f.y*w; a2 += f.z*w; a3 += f.w*w;
    }
    float* o = &g_f1p[blockIdx.x*1024];
    o[(bg*4+0)*64+j] = a0;
    o[(bg*4+1)*64+j] = a1;
    o[(bg*4+2)*64+j] = a2;
    o[(bg*4+3)*64+j] = a3;
}

// ---------------- reduce partials + dense2 + dense3 -> theta ----------------
__global__ void __launch_bounds__(256) denserest_k(const float* __restrict__ d1b,
                            const float* __restrict__ d2k, const float* __restrict__ d2b,
                            const float* __restrict__ d3k, const float* __restrict__ d3b)
{
    __shared__ float red[4][64];
    __shared__ float h1[64], h2[96];
    int b=blockIdx.x, t=threadIdx.x;  // 256 threads
    int j = t & 63, g = t>>6;
    float s = 0.f;
    #pragma unroll 4
    for (int p=g; p<D1_BLKS; p+=4) s += g_f1p[p*1024 + b*64 + j];
    red[g][j] = s;
    __syncthreads();
    if (t<64)
        h1[t] = fmaxf(red[0][t]+red[1][t]+red[2][t]+red[3][t] + d1b[t], 0.f);
    __syncthreads();
    if (t<96){
        float s2 = d2b[t];
        for (int i=0;i<64;i++) s2 += h1[i]*d2k[i*96+t];
        h2[t] = fmaxf(s2,0.f);
    }
    __syncthreads();
    if (t<6){
        float s3 = d3b[t];
        for (int i=0;i<96;i++) s3 += h2[i]*d3k[i*6+t];
        g_theta[b*8+t] = s3;
    }
}

// ---------------- grid + resize + concat + bilinear + leaky (pixel,quad layout) ----------------
__global__ void __launch_bounds__(256) sampler_k(const float* __restrict__ x,
                                                 float* __restrict__ out)
{
    int tid = threadIdx.x;
    int pix = blockIdx.x*32 + (tid>>3);
    int q = tid & 7;
    int b = pix >> 16;
    int h = (pix >> 8) & 255;
    int w = pix & 255;
    float4 t03 = *(const float4*)&g_theta[b*8];
    float2 t45 = *(const float2*)&g_theta[b*8+4];
    float gx = (float)w*(2.f/255.f) - 1.f;
    float gy = (float)h*(2.f/255.f) - 1.f;
    float tx = gx*t03.x + gy*t03.w + t03.z;
    float ty = gx*t03.y + gy*t45.x + t45.y;
    float xf = 0.5f*((tx+1.f)*255.f);
    float yf = 0.5f*((ty+1.f)*255.f);
    float x0f = floorf(xf), y0f = floorf(yf);
    float x0c = fminf(fmaxf(x0f,0.f),255.f);
    float x1c = fminf(fmaxf(x0f+1.f,0.f),255.f);
    float y0c = fminf(fmaxf(y0f,0.f),255.f);
    float y1c = fminf(fmaxf(y0f+1.f,0.f),255.f);
    float wa=(x1c-xf)*(y1c-yf), wb=(x1c-xf)*(yf-y0c);
    float wc=(xf-x0c)*(y1c-yf), wd=(xf-x0c)*(yf-y0c);
    int xi0=(int)x0c, xi1=(int)x1c, yi0=(int)y0c, yi1=(int)y1c;

    const float* xb = &g_xintp[b*32768];
    int ca = ((yi0>>3)*32 + (xi0>>3))*32;
    int cb = ((yi1>>3)*32 + (xi0>>3))*32;
    int cc = ((yi0>>3)*32 + (xi1>>3))*32;
    int cd = ((yi1>>3)*32 + (xi1>>3))*32;
    float4 Ia = *(const float4*)&xb[ca + q*4];
    float4 Ib = (cb==ca) ? Ia : *(const float4*)&xb[cb + q*4];
    float4 Ic = (cc==ca) ? Ia : *(const float4*)&xb[cc + q*4];
    float4 Id;
    if (cd==cb)      Id = Ib;
    else if (cd==cc) Id = Ic;
    else             Id = *(const float4*)&xb[cd + q*4];

    float4 val;
    val.x = wa*Ia.x + wb*Ib.x + wc*Ic.x + wd*Id.x;
    val.y = wa*Ia.y + wb*Ib.y + wc*Ic.y + wd*Id.y;
    val.z = wa*Ia.z + wb*Ib.z + wc*Ic.z + wd*Id.z;
    val.w = wa*Ia.w + wb*Ib.w + wc*Ic.w + wd*Id.w;

    if (q==0){
        const float* xb0 = x + b*65536;
        val.x = wa*xb0[yi0*256+xi0] + wb*xb0[yi1*256+xi0]
              + wc*xb0[yi0*256+xi1] + wd*xb0[yi1*256+xi1];
    }
    val.x = (val.x>=0.f)? val.x : 0.1f*val.x;
    val.y = (val.y>=0.f)? val.y : 0.1f*val.y;
    val.z = (val.z>=0.f)? val.z : 0.1f*val.z;
    val.w = (val.w>=0.f)? val.w : 0.1f*val.w;
    *(float4*)&out[pix*32 + q*4] = val;
}

extern "C" void kernel_launch(void* const* d_in, const int* in_sizes, int n_in,
                              void* d_out, int out_size)
{
    const float* x   = (const float*)d_in[0];
    const float* c1k = (const float*)d_in[1];
    const float* c1b = (const float*)d_in[2];
    const float* c2k = (const float*)d_in[3];
    const float* c2b = (const float*)d_in[4];
    const float* c3k = (const float*)d_in[5];
    const float* c3b = (const float*)d_in[6];
    const float* bng = (const float*)d_in[7];
    const float* bnb = (const float*)d_in[8];
    const float* bnm = (const float*)d_in[9];
    const float* bnv = (const float*)d_in[10];
    const float* d1k = (const float*)d_in[11];
    const float* d1b = (const float*)d_in[12];
    const float* d2k = (const float*)d_in[13];
    const float* d2b = (const float*)d_in[14];
    const float* d3k = (const float*)d_in[15];
    const float* d3b = (const float*)d_in[16];
    float* out = (float*)d_out;

    dim3 t16(16,16);
    conv1pool_k<<<dim3(8,8,16), t16>>>(x, c1k, c1b);      // launch 1
    conv2pool_k<<<dim3(4,8,16), 512>>>(c2k, c2b);         // launch 2
    conv3pool_k<<<dim3(4,4,16), 512>>>(c3k, c3b);         // launch 3
    dense1_k<<<D1_BLKS,256>>>(bng, bnb, bnm, bnv, d1k);   // launch 4 (profiled)
    denserest_k<<<16,256>>>(d1b, d2k, d2b, d3k, d3b);     // launch 5
    sampler_k<<<16*256*256/32, 256>>>(x, out);            // launch 6
}